// round 4
// baseline (speedup 1.0000x reference)
#include <cuda_runtime.h>
#include <math.h>

#define NB    128
#define H     128
#define NPG   8
#define BT    3
#define AA    243
#define PAIRS 192
#define TPB   1024
#define ABST  132

typedef unsigned long long u64;

__device__ __forceinline__ u64 pack2(float lo, float hi) {
    u64 r; asm("mov.b64 %0, {%1, %2};" : "=l"(r) : "f"(lo), "f"(hi)); return r;
}
__device__ __forceinline__ void fma2(u64& d, u64 a, u64 b) {
    asm("fma.rn.f32x2 %0, %1, %2, %0;" : "+l"(d) : "l"(a), "l"(b));
}
__device__ __forceinline__ float2 unpack2(u64 v) {
    float2 f; asm("mov.b64 {%0, %1}, %2;" : "=f"(f.x), "=f"(f.y) : "l"(v)); return f;
}

__global__ __launch_bounds__(TPB, 1)
void fused_apm_kernel(const float* __restrict__ nf,      // (1024,128)
                      const float* __restrict__ mask,    // (128,243)
                      const float* __restrict__ Wfcv1,   // (128,64)
                      const float* __restrict__ bfcv1,   // (64)
                      const float* __restrict__ Wfcv2,   // (64,1)
                      const float* __restrict__ bfcv2,   // (1)
                      const float* __restrict__ Wa2,     // (256,128)
                      const float* __restrict__ ba2,     // (128)
                      const float* __restrict__ Wfin,    // (128,3)
                      const float* __restrict__ bfin,    // (3)
                      const int*   __restrict__ idxmask, // (128,243)
                      float* __restrict__ out)           // probs[128*243] ++ readout[128]
{
    const int b = blockIdx.x;
    const int t = threadIdx.x;

    __shared__ __align__(16) u64   ps8[4][H];            // packed relu'd node pairs: 4KB
    __shared__ __align__(16) float Pt[4][2][NPG][H];     // GEMM partials [cq][grp][n][h]: 32KB
    __shared__ __align__(16) float ssum[H];
    __shared__ __align__(16) float sba[H];
    __shared__ __align__(16) float sWfT[BT][H];
    __shared__ float sc[PAIRS];
    __shared__ float red[16];
    __shared__ float wred[32];
    __shared__ float bc[2];

    // ABf (padded final AB) aliases Pt's memory; barrier-separated reduce makes it safe.
    float* ABbase = &Pt[0][0][0][0];   // ABf[grp][n][h] -> ABbase[(grp*NPG+n)*ABST + h]

    // ---- EARLY prefetch of cold tail inputs ----
    int im = 0; float mk = 0.f;
    if (t < AA) {
        im = idxmask[b * AA + t];
        mk = mask[b * AA + t];
    }

    // ---- stage node features (relu'd, node-pair packed) + small weights ----
    {
        int n = t >> 7, c = t & 127;
        float v = fmaxf(nf[(b * NPG + n) * H + c], 0.f);
        reinterpret_cast<float*>(&ps8[n >> 1][c])[n & 1] = v;
    }
    if (t < H) {
        float a = 0.f;
        #pragma unroll
        for (int n = 0; n < NPG; n++) a += nf[(b * NPG + n) * H + t];
        ssum[t] = a;
        sba[t]  = ba2[t];
    } else if (t < H + H * BT) {
        int idx = t - H;
        int h = idx & 127, k = idx >> 7;
        sWfT[k][h] = Wfin[h * BT + k];
    }
    __syncthreads();   // S1

    // ---- Ai/Bj GEMM, c-quarter split: thread = (cq, grp, h) ----
    {
        const int h   = t & 127;
        const int grp = (t >> 7) & 1;
        const int cq  = t >> 8;                       // 0..3, 32 c's each
        const float* W = Wa2 + grp * H * H + cq * 32 * H + h;
        u64 acc0 = 0, acc1 = 0, acc2 = 0, acc3 = 0;
        const ulonglong2* p0 = reinterpret_cast<const ulonglong2*>(&ps8[0][cq * 32]);
        const ulonglong2* p1 = reinterpret_cast<const ulonglong2*>(&ps8[1][cq * 32]);
        const ulonglong2* p2 = reinterpret_cast<const ulonglong2*>(&ps8[2][cq * 32]);
        const ulonglong2* p3 = reinterpret_cast<const ulonglong2*>(&ps8[3][cq * 32]);
        #pragma unroll 4
        for (int cc = 0; cc < 32; cc += 2) {
            float w0 = W[cc * H];
            float w1 = W[cc * H + H];
            u64 wp0 = pack2(w0, w0);
            u64 wp1 = pack2(w1, w1);
            ulonglong2 q;
            q = p0[cc >> 1]; fma2(acc0, q.x, wp0); fma2(acc0, q.y, wp1);
            q = p1[cc >> 1]; fma2(acc1, q.x, wp0); fma2(acc1, q.y, wp1);
            q = p2[cc >> 1]; fma2(acc2, q.x, wp0); fma2(acc2, q.y, wp1);
            q = p3[cc >> 1]; fma2(acc3, q.x, wp0); fma2(acc3, q.y, wp1);
        }
        float2 f;
        f = unpack2(acc0); Pt[cq][grp][0][h] = f.x; Pt[cq][grp][1][h] = f.y;
        f = unpack2(acc1); Pt[cq][grp][2][h] = f.x; Pt[cq][grp][3][h] = f.y;
        f = unpack2(acc2); Pt[cq][grp][4][h] = f.x; Pt[cq][grp][5][h] = f.y;
        f = unpack2(acc3); Pt[cq][grp][6][h] = f.x; Pt[cq][grp][7][h] = f.y;
    }
    __syncthreads();   // S2: Pt complete

    // ---- 4-way reduce into registers, then store into aliased padded ABf ----
    float4 rv;
    int ridx = 0;
    if (t < 512) {
        ridx = t * 4;                                 // over 2048 final floats
        const float* P0 = &Pt[0][0][0][0];
        float4 a0 = *reinterpret_cast<const float4*>(P0 + ridx);
        float4 a1 = *reinterpret_cast<const float4*>(P0 + 2048 + ridx);
        float4 a2 = *reinterpret_cast<const float4*>(P0 + 4096 + ridx);
        float4 a3 = *reinterpret_cast<const float4*>(P0 + 6144 + ridx);
        rv.x = (a0.x + a1.x) + (a2.x + a3.x);
        rv.y = (a0.y + a1.y) + (a2.y + a3.y);
        rv.z = (a0.z + a1.z) + (a2.z + a3.z);
        rv.w = (a0.w + a1.w) + (a2.w + a3.w);
    }
    __syncthreads();   // S3: all reads of Pt done
    if (t < 512) {
        int grp = ridx >> 10, n = (ridx >> 7) & 7, h = ridx & 127;
        *reinterpret_cast<float4*>(ABbase + (grp * NPG + n) * ABST + h) = rv;
    }
    __syncthreads();   // S4: ABf visible

    // ---- pair scores (threads 0-383, 2 per score) + readout (384-511, 2 per j) ----
    if (t < 2 * PAIRS) {
        const int sid  = t >> 1;
        const int half = t & 1;
        const int k = sid >> 6;
        const int p = sid & 63;
        const int i = p >> 3, j = p & 7;
        const float4* A4 = reinterpret_cast<const float4*>(ABbase + i * ABST);
        const float4* B4 = reinterpret_cast<const float4*>(ABbase + (NPG + j) * ABST);
        const float4* W4 = reinterpret_cast<const float4*>(sWfT[k]);
        const float4* Z4 = reinterpret_cast<const float4*>(sba);
        float acc0 = 0.f, acc1 = 0.f;
        const int hb = half * 16;
        #pragma unroll 8
        for (int q = 0; q < 16; q += 2) {
            float4 a, bb, w, z;
            a = A4[hb + q]; bb = B4[hb + q]; w = W4[hb + q]; z = Z4[hb + q];
            acc0 += fmaxf(a.x + bb.x + z.x, 0.f) * w.x
                  + fmaxf(a.y + bb.y + z.y, 0.f) * w.y
                  + fmaxf(a.z + bb.z + z.z, 0.f) * w.z
                  + fmaxf(a.w + bb.w + z.w, 0.f) * w.w;
            a = A4[hb + q + 1]; bb = B4[hb + q + 1]; w = W4[hb + q + 1]; z = Z4[hb + q + 1];
            acc1 += fmaxf(a.x + bb.x + z.x, 0.f) * w.x
                  + fmaxf(a.y + bb.y + z.y, 0.f) * w.y
                  + fmaxf(a.z + bb.z + z.z, 0.f) * w.z
                  + fmaxf(a.w + bb.w + z.w, 0.f) * w.w;
        }
        float acc = acc0 + acc1;
        acc += __shfl_xor_sync(0xffffffffu, acc, 1);
        if (half == 0) sc[p * BT + k] = acc + bfin[k];
    } else if (t < 512) {
        const int u    = t - 2 * PAIRS;               // 0..127
        const int j    = u >> 1;
        const int half = u & 1;
        const float4* S4 = reinterpret_cast<const float4*>(ssum);
        float acc0 = 0.f, acc1 = 0.f;
        const int cb = half * 16;
        #pragma unroll 8
        for (int q = 0; q < 16; q += 2) {
            float4 sv = S4[cb + q];
            int c = (cb + q) * 4;
            acc0 += sv.x * Wfcv1[(c + 0) * 64 + j] + sv.y * Wfcv1[(c + 1) * 64 + j]
                  + sv.z * Wfcv1[(c + 2) * 64 + j] + sv.w * Wfcv1[(c + 3) * 64 + j];
            sv = S4[cb + q + 1];
            c = (cb + q + 1) * 4;
            acc1 += sv.x * Wfcv1[(c + 0) * 64 + j] + sv.y * Wfcv1[(c + 1) * 64 + j]
                  + sv.z * Wfcv1[(c + 2) * 64 + j] + sv.w * Wfcv1[(c + 3) * 64 + j];
        }
        float tot = acc0 + acc1;
        tot += __shfl_xor_sync(0xffffffffu, tot, 1);
        float hid = (half == 0) ? fmaxf(tot + bfcv1[j], 0.f) * Wfcv2[j] : 0.f;
        #pragma unroll
        for (int off = 16; off > 0; off >>= 1)
            hid += __shfl_down_sync(0xffffffffu, hid, off);
        if ((t & 31) == 0) red[t >> 5] = hid;         // red[12..15]
    }
    __syncthreads();   // S5: sc + red visible

    if (t == 0)
        out[NB * AA + b] = ((red[12] + red[13]) + (red[14] + red[15])) + bfcv2[0];

    // ---- gather + softmax over 243 ----
    float fv = 0.f, val = -INFINITY;
    if (t < AA) {
        fv = ((im < PAIRS) ? sc[im] : 0.f) + mk;
        val = fv;
    }
    float m = val;
    #pragma unroll
    for (int off = 16; off > 0; off >>= 1)
        m = fmaxf(m, __shfl_xor_sync(0xffffffffu, m, off));
    if ((t & 31) == 0) wred[t >> 5] = m;
    __syncthreads();   // S6
    if (t < 32) {
        float v = wred[t];
        #pragma unroll
        for (int off = 16; off > 0; off >>= 1)
            v = fmaxf(v, __shfl_xor_sync(0xffffffffu, v, off));
        if (t == 0) bc[0] = v;
    }
    __syncthreads();   // S7
    float e = (t < AA) ? __expf(fv - bc[0]) : 0.f;
    float sr = e;
    #pragma unroll
    for (int off = 16; off > 0; off >>= 1)
        sr += __shfl_xor_sync(0xffffffffu, sr, off);
    if ((t & 31) == 0) wred[t >> 5] = sr;
    __syncthreads();   // S8
    if (t < 32) {
        float v = wred[t];
        #pragma unroll
        for (int off = 16; off > 0; off >>= 1)
            v += __shfl_xor_sync(0xffffffffu, v, off);
        if (t == 0) bc[1] = v;
    }
    __syncthreads();   // S9
    if (t < AA) out[b * AA + t] = e / bc[1];
}

extern "C" void kernel_launch(void* const* d_in, const int* in_sizes, int n_in,
                              void* d_out, int out_size) {
    const float* nf     = (const float*)d_in[0];
    const float* mask   = (const float*)d_in[2];
    const float* Wfcv1  = (const float*)d_in[3];
    const float* bfcv1  = (const float*)d_in[4];
    const float* Wfcv2  = (const float*)d_in[5];
    const float* bfcv2  = (const float*)d_in[6];
    const float* Wa2    = (const float*)d_in[7];
    const float* ba2    = (const float*)d_in[8];
    const float* Wfin   = (const float*)d_in[9];
    const float* bfin   = (const float*)d_in[10];
    const int*   idxm   = (const int*)d_in[11];
    float* out = (float*)d_out;

    fused_apm_kernel<<<NB, TPB>>>(nf, mask, Wfcv1, bfcv1, Wfcv2, bfcv2,
                                  Wa2, ba2, Wfin, bfin, idxm, out);
}